// round 12
// baseline (speedup 1.0000x reference)
#include <cuda_runtime.h>
#include <cstdint>

#define N_NODES 50000
#define DIM     64
#define CHUNKS  (DIM / 4)    // 16 float4 per row
#define TPE     8            // 8 threads per edge-slot: full 128B line coalescing
#define EPT_S   2            // edges per thread, scatter
#define EPT_G   4            // edges per thread, gather (16 loads in flight)

// Accumulator [N_NODES, 16] float4 = 12.8 MB (L2-resident), 16B-aligned by type.
__device__ float4 g_Mv[(size_t)N_NODES * CHUNKS];

__device__ __forceinline__ long long load_idx(const void* base, long long i, int is64) {
    if (is64) return __ldg(((const long long*)base) + i);
    return (long long)__ldg(((const int*)base) + i);
}

__device__ __forceinline__ long long bcast8(long long v) {
    return __shfl_sync(0xFFFFFFFFu, v, 0, 8);
}

// Per-block dtype probe (thread 0 checks 8 entries, broadcast via shared).
__device__ __forceinline__ int probe_is64(const void* rev, int E) {
    __shared__ int sh_is64;
    if (threadIdx.x == 0) {
        const long long* r64 = (const long long*)rev;
        int ok = 1;
        #pragma unroll
        for (int k = 0; k < 8; k++) {
            long long v = r64[k];
            if (v < 0 || v >= (long long)E) { ok = 0; break; }
        }
        sh_is64 = ok;
    }
    __syncthreads();
    return sh_is64;
}

__device__ __forceinline__ void red4(float4* p, float4 v) {
    asm volatile("red.global.add.v4.f32 [%0], {%1, %2, %3, %4};"
        :: "l"(__cvta_generic_to_global(p)),
           "f"(v.x), "f"(v.y), "f"(v.z), "f"(v.w) : "memory");
}

__device__ __forceinline__ float4 sub4(float4 a, float4 b) {
    float4 o;
    o.x = a.x - b.x; o.y = a.y - b.y; o.z = a.z - b.z; o.w = a.w - b.w;
    return o;
}

// ---------------------------------------------------------------------------
// Kernel 1: scatter-add. 8 threads/edge-slot, 2 edges/thread, 2 chunks each.
// __launch_bounds__(256,8): regs=32 suffices (REDs retire register-free).
// M reads: __ldcs evict-first (protect L2-resident M_v).
// ---------------------------------------------------------------------------
__global__ void __launch_bounds__(256, 8)
scatter_kernel(const float4* __restrict__ M4,
               const void* __restrict__ ei,
               const void* __restrict__ rev,
               int E) {
    int is64 = probe_is64(rev, E);

    int t = blockIdx.x * blockDim.x + threadIdx.x;
    long long e0 = (long long)(t >> 3) * EPT_S;
    long long e1 = e0 + 1;
    int c = t & 7;
    if (e0 >= E) return;
    bool p1 = e1 < E;

    long long d0 = 0, d1 = 0;
    if (c == 0) {
        d0 = load_idx(ei, (long long)E + e0, is64);
        if (p1) d1 = load_idx(ei, (long long)E + e1, is64);
    }
    d0 = bcast8(d0);
    d1 = bcast8(d1);

    const float4* mrow0 = M4 + (size_t)e0 * CHUNKS;
    float4 v00 = __ldcs(&mrow0[c]);
    float4 v01 = __ldcs(&mrow0[c + 8]);
    float4 v10, v11;
    if (p1) {
        const float4* mrow1 = M4 + (size_t)e1 * CHUNKS;
        v10 = __ldcs(&mrow1[c]);
        v11 = __ldcs(&mrow1[c + 8]);
    }

    float4* prow0 = g_Mv + (size_t)d0 * CHUNKS;
    red4(prow0 + c, v00);
    red4(prow0 + c + 8, v01);
    if (p1) {
        float4* prow1 = g_Mv + (size_t)d1 * CHUNKS;
        red4(prow1 + c, v10);
        red4(prow1 + c + 8, v11);
    }
}

// ---------------------------------------------------------------------------
// Kernel 2: out[e] = M_v[src[e]] - M[rev[e]].
// 8 threads/edge-slot, 4 edges/thread: 16 independent front-batched loads.
// Natural register allocation (NO launch_bounds) keeps the batch live;
// low occupancy is fine -- bytes-in-flight >> BW*latency product.
// M_v/M: __ldg. out: __stcs (write-once, evict-first).
// ---------------------------------------------------------------------------
__global__ void gather_kernel(const float4* __restrict__ M4,
                              const void* __restrict__ ei,
                              const void* __restrict__ rev,
                              float4* __restrict__ out,
                              int E) {
    int is64 = probe_is64(rev, E);

    int t = blockIdx.x * blockDim.x + threadIdx.x;
    long long base = (long long)(t >> 3) * EPT_G;
    int c = t & 7;
    if (base >= E) return;

    // Fast path: all 4 edges valid (true except the last slot).
    if (base + EPT_G <= E) {
        long long s[4], r[4];
        if (c == 0) {
            #pragma unroll
            for (int k = 0; k < 4; k++) {
                s[k] = load_idx(ei, base + k, is64);
                r[k] = load_idx(rev, base + k, is64);
            }
        }
        #pragma unroll
        for (int k = 0; k < 4; k++) { s[k] = bcast8(s[k]); r[k] = bcast8(r[k]); }

        float4 a0[4], a1[4], b0[4], b1[4];
        #pragma unroll
        for (int k = 0; k < 4; k++) {
            const float4* arow = g_Mv + (size_t)s[k] * CHUNKS;
            const float4* brow = M4 + (size_t)r[k] * CHUNKS;
            a0[k] = __ldg(&arow[c]);
            a1[k] = __ldg(&arow[c + 8]);
            b0[k] = __ldg(&brow[c]);
            b1[k] = __ldg(&brow[c + 8]);
        }
        #pragma unroll
        for (int k = 0; k < 4; k++) {
            float4* orow = out + (size_t)(base + k) * CHUNKS;
            __stcs(&orow[c], sub4(a0[k], b0[k]));
            __stcs(&orow[c + 8], sub4(a1[k], b1[k]));
        }
        return;
    }

    // Tail: per-edge guarded.
    for (long long e = base; e < E; e++) {
        long long s = 0, r = 0;
        if (c == 0) {
            s = load_idx(ei, e, is64);
            r = load_idx(rev, e, is64);
        }
        s = bcast8(s); r = bcast8(r);
        const float4* arow = g_Mv + (size_t)s * CHUNKS;
        const float4* brow = M4 + (size_t)r * CHUNKS;
        float4 a0 = __ldg(&arow[c]);
        float4 a1 = __ldg(&arow[c + 8]);
        float4 b0 = __ldg(&brow[c]);
        float4 b1 = __ldg(&brow[c + 8]);
        float4* orow = out + (size_t)e * CHUNKS;
        __stcs(&orow[c], sub4(a0, b0));
        __stcs(&orow[c + 8], sub4(a1, b1));
    }
}

// ---------------------------------------------------------------------------
// Launcher. Inputs (metadata order):
//   d_in[0] = M          float32     [E, 64]
//   d_in[1] = edge_index int64/int32 [2, E]  (row0=src, row1=dest)
//   d_in[2] = rev_index  int64/int32 [E]
//   d_in[3] = dim_size   scalar (50000, unused)
// Output: float32 [E, 64]
// ---------------------------------------------------------------------------
extern "C" void kernel_launch(void* const* d_in, const int* in_sizes, int n_in,
                              void* d_out, int out_size) {
    const float4* M4   = (const float4*)d_in[0];
    const void*   ei   = d_in[1];
    const void*   rev  = d_in[2];
    float4*       out4 = (float4*)d_out;

    const int E = in_sizes[2];

    void* mv_ptr = nullptr;
    cudaGetSymbolAddress(&mv_ptr, g_Mv);
    cudaMemsetAsync(mv_ptr, 0, (size_t)N_NODES * CHUNKS * sizeof(float4));

    {
        long long slots = ((long long)E + EPT_S - 1) / EPT_S;
        long long threads = slots * TPE;
        int tpb = 256;
        int blocks = (int)((threads + tpb - 1) / tpb);
        scatter_kernel<<<blocks, tpb>>>(M4, ei, rev, E);
    }
    {
        long long slots = ((long long)E + EPT_G - 1) / EPT_G;
        long long threads = slots * TPE;
        int tpb = 256;
        int blocks = (int)((threads + tpb - 1) / tpb);
        gather_kernel<<<blocks, tpb>>>(M4, ei, rev, out4, E);
    }
}

// round 13
// speedup vs baseline: 1.2895x; 1.2895x over previous
#include <cuda_runtime.h>
#include <cstdint>

#define N_NODES 50000
#define DIM     64
#define CHUNKS  (DIM / 4)    // 16 float4 per row
#define TPE     8            // 8 threads per edge-slot: full 128B line coalescing
#define EPT_G   2            // edges per thread in gather (measured optimum)

// Accumulator [N_NODES, 16] float4 = 12.8 MB (L2-resident), 16B-aligned by type.
__device__ float4 g_Mv[(size_t)N_NODES * CHUNKS];

__device__ __forceinline__ long long load_idx(const void* base, long long i, int is64) {
    if (is64) return __ldg(((const long long*)base) + i);
    return (long long)__ldg(((const int*)base) + i);
}

__device__ __forceinline__ long long bcast8(long long v) {
    return __shfl_sync(0xFFFFFFFFu, v, 0, 8);
}

// Per-block dtype probe (thread 0 checks 8 entries, broadcast via shared).
__device__ __forceinline__ int probe_is64(const void* rev, int E) {
    __shared__ int sh_is64;
    if (threadIdx.x == 0) {
        const long long* r64 = (const long long*)rev;
        int ok = 1;
        #pragma unroll
        for (int k = 0; k < 8; k++) {
            long long v = r64[k];
            if (v < 0 || v >= (long long)E) { ok = 0; break; }
        }
        sh_is64 = ok;
    }
    __syncthreads();
    return sh_is64;
}

__device__ __forceinline__ void red4(float4* p, float4 v) {
    asm volatile("red.global.add.v4.f32 [%0], {%1, %2, %3, %4};"
        :: "l"(__cvta_generic_to_global(p)),
           "f"(v.x), "f"(v.y), "f"(v.z), "f"(v.w) : "memory");
}

// ---------------------------------------------------------------------------
// Kernel 1: scatter-add (R8 config: 1 edge per 8-thread slot, 2 chunks each).
// M reads: __ldcs evict-first (protect L2-resident M_v accumulator).
// red.global.add.v4.f32: one 16B L2-side reduction per chunk.
// ---------------------------------------------------------------------------
__global__ void scatter_kernel(const float4* __restrict__ M4,
                               const void* __restrict__ ei,
                               const void* __restrict__ rev,
                               int E) {
    int is64 = probe_is64(rev, E);

    int t = blockIdx.x * blockDim.x + threadIdx.x;
    int e = t >> 3;
    int c = t & 7;
    if (e >= E) return;

    long long d = 0;
    if (c == 0) d = load_idx(ei, (long long)E + e, is64);   // dest
    d = bcast8(d);

    const float4* mrow = M4 + (size_t)e * CHUNKS;
    float4 v0 = __ldcs(&mrow[c]);
    float4 v1 = __ldcs(&mrow[c + 8]);

    float4* prow = g_Mv + (size_t)d * CHUNKS;
    red4(prow + c, v0);
    red4(prow + c + 8, v1);
}

// ---------------------------------------------------------------------------
// Kernel 2: out[e] = M_v[src[e]] - M[rev[e]] (R8/R10 measured-best config:
// 8 threads/edge-slot, 2 edges/thread, natural regs=40 keeps all 8
// front-batched loads live). M_v/M: __ldg. out: __stcs (write-once).
// ---------------------------------------------------------------------------
__global__ void gather_kernel(const float4* __restrict__ M4,
                              const void* __restrict__ ei,
                              const void* __restrict__ rev,
                              float4* __restrict__ out,
                              int E) {
    int is64 = probe_is64(rev, E);

    int t = blockIdx.x * blockDim.x + threadIdx.x;
    long long e0 = (long long)(t >> 3) * EPT_G;
    long long e1 = e0 + 1;
    int c = t & 7;
    if (e0 >= E) return;
    bool p1 = e1 < E;

    long long s0 = 0, r0 = 0, s1 = 0, r1 = 0;
    if (c == 0) {
        s0 = load_idx(ei, e0, is64);
        r0 = load_idx(rev, e0, is64);
        if (p1) {
            s1 = load_idx(ei, e1, is64);
            r1 = load_idx(rev, e1, is64);
        }
    }
    s0 = bcast8(s0); r0 = bcast8(r0);
    s1 = bcast8(s1); r1 = bcast8(r1);

    const float4* arow0 = g_Mv + (size_t)s0 * CHUNKS;
    const float4* brow0 = M4 + (size_t)r0 * CHUNKS;

    float4 a00 = __ldg(&arow0[c]);
    float4 a01 = __ldg(&arow0[c + 8]);
    float4 b00 = __ldg(&brow0[c]);
    float4 b01 = __ldg(&brow0[c + 8]);

    float4 a10, a11, b10, b11;
    if (p1) {
        const float4* arow1 = g_Mv + (size_t)s1 * CHUNKS;
        const float4* brow1 = M4 + (size_t)r1 * CHUNKS;
        a10 = __ldg(&arow1[c]);
        a11 = __ldg(&arow1[c + 8]);
        b10 = __ldg(&brow1[c]);
        b11 = __ldg(&brow1[c + 8]);
    }

    float4 o;
    float4* orow0 = out + (size_t)e0 * CHUNKS;
    o.x = a00.x - b00.x; o.y = a00.y - b00.y; o.z = a00.z - b00.z; o.w = a00.w - b00.w;
    __stcs(&orow0[c], o);
    o.x = a01.x - b01.x; o.y = a01.y - b01.y; o.z = a01.z - b01.z; o.w = a01.w - b01.w;
    __stcs(&orow0[c + 8], o);

    if (p1) {
        float4* orow1 = out + (size_t)e1 * CHUNKS;
        o.x = a10.x - b10.x; o.y = a10.y - b10.y; o.z = a10.z - b10.z; o.w = a10.w - b10.w;
        __stcs(&orow1[c], o);
        o.x = a11.x - b11.x; o.y = a11.y - b11.y; o.z = a11.z - b11.z; o.w = a11.w - b11.w;
        __stcs(&orow1[c + 8], o);
    }
}

// ---------------------------------------------------------------------------
// Launcher. Inputs (metadata order):
//   d_in[0] = M          float32     [E, 64]
//   d_in[1] = edge_index int64/int32 [2, E]  (row0=src, row1=dest)
//   d_in[2] = rev_index  int64/int32 [E]
//   d_in[3] = dim_size   scalar (50000, unused)
// Output: float32 [E, 64]
// ---------------------------------------------------------------------------
extern "C" void kernel_launch(void* const* d_in, const int* in_sizes, int n_in,
                              void* d_out, int out_size) {
    const float4* M4   = (const float4*)d_in[0];
    const void*   ei   = d_in[1];
    const void*   rev  = d_in[2];
    float4*       out4 = (float4*)d_out;

    const int E = in_sizes[2];

    void* mv_ptr = nullptr;
    cudaGetSymbolAddress(&mv_ptr, g_Mv);
    cudaMemsetAsync(mv_ptr, 0, (size_t)N_NODES * CHUNKS * sizeof(float4));

    {
        long long threads = (long long)E * TPE;       // 1 edge per slot
        int tpb = 256;
        int blocks = (int)((threads + tpb - 1) / tpb);
        scatter_kernel<<<blocks, tpb>>>(M4, ei, rev, E);
    }
    {
        long long slots = ((long long)E + EPT_G - 1) / EPT_G;
        long long threads = slots * TPE;
        int tpb = 256;
        int blocks = (int)((threads + tpb - 1) / tpb);
        gather_kernel<<<blocks, tpb>>>(M4, ei, rev, out4, E);
    }
}

// round 14
// speedup vs baseline: 1.2922x; 1.0021x over previous
#include <cuda_runtime.h>
#include <cstdint>

#define N_NODES 50000
#define DIM     64
#define CHUNKS  (DIM / 4)    // 16 float4 per row
#define TPE     8            // 8 threads per edge-slot: full 128B line coalescing
#define EPT_G   2            // edges per thread in gather (measured optimum)

// Accumulator [N_NODES, 16] float4 = 12.8 MB (L2-resident), 16B-aligned by type.
__device__ float4 g_Mv[(size_t)N_NODES * CHUNKS];

__device__ __forceinline__ long long load_idx(const void* base, long long i, int is64) {
    if (is64) return __ldg(((const long long*)base) + i);
    return (long long)__ldg(((const int*)base) + i);
}

__device__ __forceinline__ long long bcast8(long long v) {
    return __shfl_sync(0xFFFFFFFFu, v, 0, 8);
}

// Per-block dtype probe (thread 0 checks 8 entries, broadcast via shared).
__device__ __forceinline__ int probe_is64(const void* rev, int E) {
    __shared__ int sh_is64;
    if (threadIdx.x == 0) {
        const long long* r64 = (const long long*)rev;
        int ok = 1;
        #pragma unroll
        for (int k = 0; k < 8; k++) {
            long long v = r64[k];
            if (v < 0 || v >= (long long)E) { ok = 0; break; }
        }
        sh_is64 = ok;
    }
    __syncthreads();
    return sh_is64;
}

__device__ __forceinline__ void red4(float4* p, float4 v) {
    asm volatile("red.global.add.v4.f32 [%0], {%1, %2, %3, %4};"
        :: "l"(__cvta_generic_to_global(p)),
           "f"(v.x), "f"(v.y), "f"(v.z), "f"(v.w) : "memory");
}

// ---------------------------------------------------------------------------
// Kernel 1: scatter-add (1 edge per 8-thread slot, 2 chunks each).
// M reads issued before destination address math. __ldcs evict-first
// (protect L2-resident M_v). red.global.add.v4.f32 = 16B L2-side RED.
// ---------------------------------------------------------------------------
__global__ void scatter_kernel(const float4* __restrict__ M4,
                               const void* __restrict__ ei,
                               const void* __restrict__ rev,
                               int E) {
    int is64 = probe_is64(rev, E);

    int t = blockIdx.x * blockDim.x + threadIdx.x;
    int e = t >> 3;
    int c = t & 7;
    if (e >= E) return;

    // Issue the streaming DRAM loads first (independent of the index).
    const float4* mrow = M4 + (size_t)e * CHUNKS;
    float4 v0 = __ldcs(&mrow[c]);
    float4 v1 = __ldcs(&mrow[c + 8]);

    long long d = 0;
    if (c == 0) d = load_idx(ei, (long long)E + e, is64);   // dest
    d = bcast8(d);

    float4* prow = g_Mv + (size_t)d * CHUNKS;
    red4(prow + c, v0);
    red4(prow + c + 8, v1);
}

// ---------------------------------------------------------------------------
// Kernel 2: out[e] = M_v[src[e]] - M[rev[e]].
// 8 threads/edge-slot, 2 edges/thread, natural regs keep all 8 loads live.
// DRAM-latency b-loads (M[rev], random rows) issued BEFORE L2-hit a-loads
// (M_v) so the long fills start earliest in the L1tex queue.
// out: __stcs (write-once, evict-first).
// ---------------------------------------------------------------------------
__global__ void gather_kernel(const float4* __restrict__ M4,
                              const void* __restrict__ ei,
                              const void* __restrict__ rev,
                              float4* __restrict__ out,
                              int E) {
    int is64 = probe_is64(rev, E);

    int t = blockIdx.x * blockDim.x + threadIdx.x;
    long long e0 = (long long)(t >> 3) * EPT_G;
    long long e1 = e0 + 1;
    int c = t & 7;
    if (e0 >= E) return;
    bool p1 = e1 < E;

    long long s0 = 0, r0 = 0, s1 = 0, r1 = 0;
    if (c == 0) {
        r0 = load_idx(rev, e0, is64);
        s0 = load_idx(ei, e0, is64);
        if (p1) {
            r1 = load_idx(rev, e1, is64);
            s1 = load_idx(ei, e1, is64);
        }
    }
    r0 = bcast8(r0); s0 = bcast8(s0);
    r1 = bcast8(r1); s1 = bcast8(s1);

    const float4* brow0 = M4 + (size_t)r0 * CHUNKS;
    const float4* brow1 = M4 + (size_t)r1 * CHUNKS;
    const float4* arow0 = g_Mv + (size_t)s0 * CHUNKS;
    const float4* arow1 = g_Mv + (size_t)s1 * CHUNKS;

    // DRAM-bound loads first
    float4 b00 = __ldg(&brow0[c]);
    float4 b01 = __ldg(&brow0[c + 8]);
    float4 b10, b11;
    if (p1) {
        b10 = __ldg(&brow1[c]);
        b11 = __ldg(&brow1[c + 8]);
    }
    // L2-hit loads second (overlap the DRAM shadow)
    float4 a00 = __ldg(&arow0[c]);
    float4 a01 = __ldg(&arow0[c + 8]);
    float4 a10, a11;
    if (p1) {
        a10 = __ldg(&arow1[c]);
        a11 = __ldg(&arow1[c + 8]);
    }

    float4 o;
    float4* orow0 = out + (size_t)e0 * CHUNKS;
    o.x = a00.x - b00.x; o.y = a00.y - b00.y; o.z = a00.z - b00.z; o.w = a00.w - b00.w;
    __stcs(&orow0[c], o);
    o.x = a01.x - b01.x; o.y = a01.y - b01.y; o.z = a01.z - b01.z; o.w = a01.w - b01.w;
    __stcs(&orow0[c + 8], o);

    if (p1) {
        float4* orow1 = out + (size_t)e1 * CHUNKS;
        o.x = a10.x - b10.x; o.y = a10.y - b10.y; o.z = a10.z - b10.z; o.w = a10.w - b10.w;
        __stcs(&orow1[c], o);
        o.x = a11.x - b11.x; o.y = a11.y - b11.y; o.z = a11.z - b11.z; o.w = a11.w - b11.w;
        __stcs(&orow1[c + 8], o);
    }
}

// ---------------------------------------------------------------------------
// Launcher. Inputs (metadata order):
//   d_in[0] = M          float32     [E, 64]
//   d_in[1] = edge_index int64/int32 [2, E]  (row0=src, row1=dest)
//   d_in[2] = rev_index  int64/int32 [E]
//   d_in[3] = dim_size   scalar (50000, unused)
// Output: float32 [E, 64]
// ---------------------------------------------------------------------------
extern "C" void kernel_launch(void* const* d_in, const int* in_sizes, int n_in,
                              void* d_out, int out_size) {
    const float4* M4   = (const float4*)d_in[0];
    const void*   ei   = d_in[1];
    const void*   rev  = d_in[2];
    float4*       out4 = (float4*)d_out;

    const int E = in_sizes[2];

    void* mv_ptr = nullptr;
    cudaGetSymbolAddress(&mv_ptr, g_Mv);
    cudaMemsetAsync(mv_ptr, 0, (size_t)N_NODES * CHUNKS * sizeof(float4));

    {
        long long threads = (long long)E * TPE;       // 1 edge per slot
        int tpb = 256;
        int blocks = (int)((threads + tpb - 1) / tpb);
        scatter_kernel<<<blocks, tpb>>>(M4, ei, rev, E);
    }
    {
        long long slots = ((long long)E + EPT_G - 1) / EPT_G;
        long long threads = slots * TPE;
        int tpb = 256;
        int blocks = (int)((threads + tpb - 1) / tpb);
        gather_kernel<<<blocks, tpb>>>(M4, ei, rev, out4, E);
    }
}